// round 2
// baseline (speedup 1.0000x reference)
#include <cuda_runtime.h>

#define N_NODES 64000
#define N_EDGES 1024000
#define F 64
#define N_GRAPHS 128
#define FS 65  // padded stride for transposed weights (avoid bank conflicts)

// ---------------- persistent device scratch ----------------
__device__ int   g_is64;               // 1 if edge/batch indices are int64, 0 if int32
__device__ int   g_deg[N_NODES];
__device__ int   g_rowptr[N_NODES + 1];
__device__ int   g_cursor[N_NODES];
__device__ int   g_col[N_EDGES];
__device__ float g_invdeg[N_NODES];

__device__ __align__(16) float g_yl[N_NODES * F];   // h @ Wl.T
__device__ __align__(16) float g_yr[N_NODES * F];   // h @ Wr.T
__device__ __align__(16) float g_h[N_NODES * F];    // layer output

__device__ __align__(16) float g_y2l[N_NODES * 2];
__device__ __align__(16) float g_y2r[N_NODES * 2];
__device__ float g_gsum[N_GRAPHS * 2];
__device__ int   g_gcnt[N_GRAPHS];

// flag-dispatched integer accessor (handles int64 or int32 input arrays)
__device__ __forceinline__ int idx_at(const void* p, int i) {
    if (g_is64) return (int)((const long long*)p)[i];
    return ((const int*)p)[i];
}

// ---------------- dtype probe ----------------
__global__ void k_detect(const void* __restrict__ ei) {
    if (threadIdx.x == 0 && blockIdx.x == 0) {
        const long long* p = (const long long*)ei;
        int ok = 1;
        #pragma unroll 1
        for (int i = 0; i < 64; i++) {
            long long v = p[i];
            if (v < 0 || v >= (long long)N_NODES) { ok = 0; break; }
        }
        g_is64 = ok;
    }
}

// ---------------- CSR build ----------------
__global__ void k_init() {
    int i = blockIdx.x * blockDim.x + threadIdx.x;
    if (i < N_NODES) g_deg[i] = 0;
    if (i < N_GRAPHS * 2) g_gsum[i] = 0.0f;
    if (i < N_GRAPHS) g_gcnt[i] = 0;
}

__global__ void k_count(const void* __restrict__ ei,
                        const void* __restrict__ batch) {
    int i = blockIdx.x * blockDim.x + threadIdx.x;
    if (i < N_EDGES) {
        int dst = idx_at(ei, N_EDGES + i);
        atomicAdd(&g_deg[dst], 1);
    }
    if (i < N_NODES) {
        atomicAdd(&g_gcnt[idx_at(batch, i)], 1);
    }
}

// single-block exclusive scan over 64000 degrees (1024 threads x 63 chunk)
__global__ void k_scan() {
    const int T = 1024, CH = 63;
    __shared__ int ssum[T];
    int t = threadIdx.x;
    int base = t * CH;
    int s = 0;
    for (int j = 0; j < CH; j++) {
        int i = base + j;
        if (i < N_NODES) s += g_deg[i];
    }
    ssum[t] = s;
    __syncthreads();
    for (int off = 1; off < T; off <<= 1) {
        int v = ssum[t];
        int add = (t >= off) ? ssum[t - off] : 0;
        __syncthreads();
        ssum[t] = v + add;
        __syncthreads();
    }
    int run = (t == 0) ? 0 : ssum[t - 1];
    for (int j = 0; j < CH; j++) {
        int i = base + j;
        if (i < N_NODES) {
            g_rowptr[i] = run;
            g_cursor[i] = run;
            int d = g_deg[i];
            g_invdeg[i] = (d > 0) ? (1.0f / (float)d) : 0.0f;
            run += d;
        }
    }
    if (t == T - 1) g_rowptr[N_NODES] = run;
}

__global__ void k_fill(const void* __restrict__ ei) {
    int i = blockIdx.x * blockDim.x + threadIdx.x;
    if (i < N_EDGES) {
        int dst = idx_at(ei, N_EDGES + i);
        int src = idx_at(ei, i);
        int p = atomicAdd(&g_cursor[dst], 1);
        g_col[p] = src;
    }
}

// ---------------- dense transform: yl = h @ Wl.T, yr = h @ Wr.T ----------------
// use_x: 1 -> read external x pointer, 0 -> read g_h
__global__ void k_transform(const float* __restrict__ x_ext, int use_x,
                            const float* __restrict__ Wl,
                            const float* __restrict__ Wr) {
    __shared__ float sWl[F * FS];  // transposed: sWl[k*FS + c] = Wl[c*F + k]
    __shared__ float sWr[F * FS];
    const float* h = use_x ? x_ext : g_h;
    int t = threadIdx.x;
    for (int idx = t; idx < F * F; idx += 256) {
        int c = idx >> 6, k = idx & 63;
        sWl[k * FS + c] = Wl[idx];
        sWr[k * FS + c] = Wr[idx];
    }
    __syncthreads();

    int c = t & 63;
    int slot = t >> 6;  // 0..3
    int nodeBase = blockIdx.x * 32;
    #pragma unroll 1
    for (int g = 0; g < 8; g++) {
        int node = nodeBase + g * 4 + slot;
        if (node >= N_NODES) return;
        const float* hr = h + node * F;
        float al = 0.0f, ar = 0.0f;
        #pragma unroll
        for (int k = 0; k < F; k++) {
            float hv = __ldg(hr + k);  // broadcast across the 64 c-threads
            al = fmaf(hv, sWl[k * FS + c], al);
            ar = fmaf(hv, sWr[k * FS + c], ar);
        }
        g_yl[node * F + c] = al;
        g_yr[node * F + c] = ar;
    }
}

// ---------------- aggregate + epilogue: h = relu(invdeg * sum yl[src] + yr + b) ----------------
__global__ void k_aggr(const float* __restrict__ b) {
    int warp = (blockIdx.x * blockDim.x + threadIdx.x) >> 5;
    int lane = threadIdx.x & 31;
    if (warp >= N_NODES) return;
    int s0 = g_rowptr[warp];
    int s1 = g_rowptr[warp + 1];
    float ax = 0.0f, ay = 0.0f;
    int j = s0;
    for (; j + 4 <= s1; j += 4) {
        int i0 = g_col[j + 0];
        int i1 = g_col[j + 1];
        int i2 = g_col[j + 2];
        int i3 = g_col[j + 3];
        float2 v0 = *(const float2*)(g_yl + i0 * F + lane * 2);
        float2 v1 = *(const float2*)(g_yl + i1 * F + lane * 2);
        float2 v2 = *(const float2*)(g_yl + i2 * F + lane * 2);
        float2 v3 = *(const float2*)(g_yl + i3 * F + lane * 2);
        ax += (v0.x + v1.x) + (v2.x + v3.x);
        ay += (v0.y + v1.y) + (v2.y + v3.y);
    }
    for (; j < s1; j++) {
        int i0 = g_col[j];
        float2 v0 = *(const float2*)(g_yl + i0 * F + lane * 2);
        ax += v0.x;
        ay += v0.y;
    }
    float id = g_invdeg[warp];
    float2 r = *(const float2*)(g_yr + warp * F + lane * 2);
    float b0 = b[lane * 2], b1 = b[lane * 2 + 1];
    float o0 = fmaxf(ax * id + r.x + b0, 0.0f);
    float o1 = fmaxf(ay * id + r.y + b1, 0.0f);
    *(float2*)(g_h + warp * F + lane * 2) = make_float2(o0, o1);
}

// ---------------- output layer transform: 4 outputs per node ----------------
__global__ void k_transform_out(const float* __restrict__ Wlo,
                                const float* __restrict__ Wro) {
    __shared__ float sW[4 * F];
    int t = threadIdx.x;
    if (t < 128) sW[t] = Wlo[t];
    else if (t < 256) sW[t] = Wro[t - 128];
    __syncthreads();
    int i = blockIdx.x * blockDim.x + t;
    if (i >= N_NODES) return;
    const float4* hr = (const float4*)(g_h + i * F);
    float a0 = 0, a1 = 0, r0 = 0, r1 = 0;
    #pragma unroll
    for (int q = 0; q < 16; q++) {
        float4 hv = hr[q];
        int k = q * 4;
        a0 += hv.x * sW[0 * F + k] + hv.y * sW[0 * F + k + 1] + hv.z * sW[0 * F + k + 2] + hv.w * sW[0 * F + k + 3];
        a1 += hv.x * sW[1 * F + k] + hv.y * sW[1 * F + k + 1] + hv.z * sW[1 * F + k + 2] + hv.w * sW[1 * F + k + 3];
        r0 += hv.x * sW[2 * F + k] + hv.y * sW[2 * F + k + 1] + hv.z * sW[2 * F + k + 2] + hv.w * sW[2 * F + k + 3];
        r1 += hv.x * sW[3 * F + k] + hv.y * sW[3 * F + k + 1] + hv.z * sW[3 * F + k + 2] + hv.w * sW[3 * F + k + 3];
    }
    g_y2l[i * 2 + 0] = a0;
    g_y2l[i * 2 + 1] = a1;
    g_y2r[i * 2 + 0] = r0;
    g_y2r[i * 2 + 1] = r1;
}

// ---------------- output aggregation + graph pooling accumulate ----------------
__global__ void k_aggr_out(const void* __restrict__ batch,
                           const float* __restrict__ b_out) {
    int i = blockIdx.x * blockDim.x + threadIdx.x;
    if (i >= N_NODES) return;
    int s0 = g_rowptr[i];
    int s1 = g_rowptr[i + 1];
    float a0 = 0.0f, a1 = 0.0f;
    for (int j = s0; j < s1; j++) {
        int src = g_col[j];
        float2 v = *(const float2*)(g_y2l + src * 2);
        a0 += v.x;
        a1 += v.y;
    }
    float id = g_invdeg[i];
    float o0 = a0 * id + g_y2r[i * 2 + 0] + b_out[0];
    float o1 = a1 * id + g_y2r[i * 2 + 1] + b_out[1];
    int g = idx_at(batch, i);
    atomicAdd(&g_gsum[g * 2 + 0], o0);
    atomicAdd(&g_gsum[g * 2 + 1], o1);
}

__global__ void k_final(float* __restrict__ out) {
    int i = threadIdx.x;
    if (i < N_GRAPHS * 2) {
        int g = i >> 1;
        float c = (float)max(g_gcnt[g], 1);
        out[i] = g_gsum[i] / c;
    }
}

// ---------------- launch ----------------
extern "C" void kernel_launch(void* const* d_in, const int* in_sizes, int n_in,
                              void* d_out, int out_size) {
    const float* x      = (const float*)d_in[0];
    const void*  ei     = d_in[1];   // int64 or int32 [2, E]
    const void*  batch  = d_in[2];   // int64 or int32 [N]
    const float* Wl     = (const float*)d_in[3];   // [3,64,64]
    const float* Wr     = (const float*)d_in[4];   // [3,64,64]
    const float* b      = (const float*)d_in[5];   // [3,64]
    const float* Wl_out = (const float*)d_in[6];   // [2,64]
    const float* Wr_out = (const float*)d_in[7];   // [2,64]
    const float* b_out  = (const float*)d_in[8];   // [2]
    float*       out    = (float*)d_out;

    // dtype probe + CSR build (once per launch; graph fixed across layers)
    k_detect<<<1, 32>>>(ei);
    k_init<<<(N_NODES + 255) / 256, 256>>>();
    k_count<<<(N_EDGES + 255) / 256, 256>>>(ei, batch);
    k_scan<<<1, 1024>>>();
    k_fill<<<(N_EDGES + 255) / 256, 256>>>(ei);

    const int TGRID = (N_NODES + 31) / 32;
    const int AGRID = (N_NODES * 32 + 255) / 256;

    // 3 hidden SAGEConv layers: transform-then-aggregate (aggregation commutes with Wl)
    k_transform<<<TGRID, 256>>>(x, 1, Wl + 0 * F * F, Wr + 0 * F * F);
    k_aggr<<<AGRID, 256>>>(b + 0 * F);
    k_transform<<<TGRID, 256>>>(x, 0, Wl + 1 * F * F, Wr + 1 * F * F);
    k_aggr<<<AGRID, 256>>>(b + 1 * F);
    k_transform<<<TGRID, 256>>>(x, 0, Wl + 2 * F * F, Wr + 2 * F * F);
    k_aggr<<<AGRID, 256>>>(b + 2 * F);

    // output layer + global mean pool
    k_transform_out<<<(N_NODES + 255) / 256, 256>>>(Wl_out, Wr_out);
    k_aggr_out<<<(N_NODES + 255) / 256, 256>>>(batch, b_out);
    k_final<<<1, 256>>>(out);
}

// round 3
// speedup vs baseline: 1.7893x; 1.7893x over previous
#include <cuda_runtime.h>

#define N_NODES 64000
#define N_EDGES 1024000
#define F 64
#define N_GRAPHS 128
#define SCAN_NB 250   // 250 * 256 == 64000

// ---------------- persistent device scratch ----------------
__device__ int   g_is64;               // 1 if edge/batch indices are int64, 0 if int32
__device__ int   g_deg[N_NODES];
__device__ int   g_rowptr[N_NODES + 1];
__device__ int   g_cursor[N_NODES];
__device__ int   g_col[N_EDGES];
__device__ float g_invdeg[N_NODES];
__device__ int   g_bsum[SCAN_NB];
__device__ int   g_boff[SCAN_NB];

__device__ __align__(16) float g_yl[N_NODES * F];   // h @ Wl.T
__device__ __align__(16) float g_yr[N_NODES * F];   // h @ Wr.T
__device__ __align__(16) float g_h[N_NODES * F];    // layer output

__device__ __align__(16) float g_y2l[N_NODES * 2];
__device__ __align__(16) float g_y2r[N_NODES * 2];
__device__ float g_gsum[N_GRAPHS * 2];
__device__ int   g_gcnt[N_GRAPHS];

// flag-dispatched integer accessor (handles int64 or int32 input arrays)
__device__ __forceinline__ int idx_at(const void* p, int i) {
    if (g_is64) return (int)((const long long*)p)[i];
    return ((const int*)p)[i];
}

// ---------------- dtype probe ----------------
__global__ void k_detect(const void* __restrict__ ei) {
    if (threadIdx.x == 0 && blockIdx.x == 0) {
        const long long* p = (const long long*)ei;
        int ok = 1;
        #pragma unroll 1
        for (int i = 0; i < 64; i++) {
            long long v = p[i];
            if (v < 0 || v >= (long long)N_NODES) { ok = 0; break; }
        }
        g_is64 = ok;
    }
}

// ---------------- CSR build ----------------
__global__ void k_init() {
    int i = blockIdx.x * blockDim.x + threadIdx.x;
    if (i < N_NODES) g_deg[i] = 0;
    if (i < N_GRAPHS * 2) g_gsum[i] = 0.0f;
    if (i < N_GRAPHS) g_gcnt[i] = 0;
}

__global__ void k_count(const void* __restrict__ ei,
                        const void* __restrict__ batch) {
    int i = blockIdx.x * blockDim.x + threadIdx.x;
    if (i < N_EDGES) {
        int dst = idx_at(ei, N_EDGES + i);
        atomicAdd(&g_deg[dst], 1);
    }
    if (i < N_NODES) {
        atomicAdd(&g_gcnt[idx_at(batch, i)], 1);
    }
}

// inclusive block scan over 256 elements (shuffle + smem)
__device__ __forceinline__ int block_scan_incl(int v) {
    int t = threadIdx.x, lane = t & 31, w = t >> 5;
    #pragma unroll
    for (int o = 1; o < 32; o <<= 1) {
        int n = __shfl_up_sync(0xffffffffu, v, o);
        if (lane >= o) v += n;
    }
    __shared__ int ws[8];
    if (lane == 31) ws[w] = v;
    __syncthreads();
    int add = 0;
    #pragma unroll
    for (int i = 0; i < 8; i++)
        if (i < w) add += ws[i];
    return v + add;
}

// phase 1: per-block sums of 256 degrees
__global__ void k_scan1() {
    int t = threadIdx.x, b = blockIdx.x;
    int v = g_deg[b * 256 + t];
    #pragma unroll
    for (int o = 16; o > 0; o >>= 1) v += __shfl_down_sync(0xffffffffu, v, o);
    __shared__ int ws[8];
    if ((t & 31) == 0) ws[t >> 5] = v;
    __syncthreads();
    if (t == 0) {
        int s = 0;
        #pragma unroll
        for (int i = 0; i < 8; i++) s += ws[i];
        g_bsum[b] = s;
    }
}

// phase 2: exclusive scan of the 250 block sums (one block)
__global__ void k_scan2() {
    int t = threadIdx.x;
    int v = (t < SCAN_NB) ? g_bsum[t] : 0;
    int incl = block_scan_incl(v);
    if (t < SCAN_NB) g_boff[t] = incl - v;
}

// phase 3: block-local exclusive scan + global offset -> rowptr/cursor/invdeg
__global__ void k_scan3() {
    int t = threadIdx.x, b = blockIdx.x;
    int i = b * 256 + t;
    int d = g_deg[i];
    int incl = block_scan_incl(d);
    int excl = incl - d + g_boff[b];
    g_rowptr[i] = excl;
    g_cursor[i] = excl;
    g_invdeg[i] = (d > 0) ? (1.0f / (float)d) : 0.0f;
    if (i == N_NODES - 1) g_rowptr[N_NODES] = excl + d;
}

__global__ void k_fill(const void* __restrict__ ei) {
    int i = blockIdx.x * blockDim.x + threadIdx.x;
    if (i < N_EDGES) {
        int dst = idx_at(ei, N_EDGES + i);
        int src = idx_at(ei, i);
        int p = atomicAdd(&g_cursor[dst], 1);
        g_col[p] = src;
    }
}

// ---------------- dense transform: yl = h @ Wl.T, yr = h @ Wr.T ----------------
// 16x16 threads, 64-node x 64-col tile, 4x4 register tile per thread.
// smem staged k-major so A/B fragments are single LDS.128s. All strides 64 floats
// (256B rows): fragment reads conflict-free, transpose stores conflict-free.
__global__ void __launch_bounds__(256) k_transform(
        const float* __restrict__ x_ext, int use_x,
        const float* __restrict__ Wl,
        const float* __restrict__ Wr) {
    __shared__ float sH[F * F];    // sH[k*64 + node]
    __shared__ float sWl[F * F];   // sWl[k*64 + c] = Wl[c*64 + k]
    __shared__ float sWr[F * F];
    const float* h = use_x ? x_ext : g_h;
    int t = threadIdx.x;
    int base = blockIdx.x * 64;

    // stage weights transposed: idx -> (c = idx&63, k = idx>>6); smem stores are
    // consecutive-c per warp (conflict-free); global reads hit L1 after 1st warp.
    for (int idx = t; idx < F * F; idx += 256) {
        int c = idx & 63, k = idx >> 6;
        sWl[k * F + c] = Wl[c * F + k];
        sWr[k * F + c] = Wr[c * F + k];
    }
    // stage feature tile transposed: thread (n = t&63, kq = t>>6) loads float4s
    {
        int n = t & 63, kq = t >> 6;
        const float* hrow = h + (size_t)(base + n) * F;
        #pragma unroll
        for (int j = 0; j < 4; j++) {
            int kk = (kq + j * 4) * 4;
            float4 v = *(const float4*)(hrow + kk);
            sH[(kk + 0) * F + n] = v.x;
            sH[(kk + 1) * F + n] = v.y;
            sH[(kk + 2) * F + n] = v.z;
            sH[(kk + 3) * F + n] = v.w;
        }
    }
    __syncthreads();

    int tx = t & 15, ty = t >> 4;   // col group / node group
    float al[4][4], ar[4][4];
    #pragma unroll
    for (int i = 0; i < 4; i++)
        #pragma unroll
        for (int j = 0; j < 4; j++) { al[i][j] = 0.0f; ar[i][j] = 0.0f; }

    #pragma unroll 8
    for (int k = 0; k < F; k++) {
        float4 a  = *(const float4*)&sH [k * F + ty * 4];
        float4 bl = *(const float4*)&sWl[k * F + tx * 4];
        float4 br = *(const float4*)&sWr[k * F + tx * 4];
        float av[4] = {a.x, a.y, a.z, a.w};
        float blv[4] = {bl.x, bl.y, bl.z, bl.w};
        float brv[4] = {br.x, br.y, br.z, br.w};
        #pragma unroll
        for (int i = 0; i < 4; i++)
            #pragma unroll
            for (int j = 0; j < 4; j++) {
                al[i][j] = fmaf(av[i], blv[j], al[i][j]);
                ar[i][j] = fmaf(av[i], brv[j], ar[i][j]);
            }
    }

    #pragma unroll
    for (int i = 0; i < 4; i++) {
        int node = base + ty * 4 + i;
        *(float4*)(g_yl + (size_t)node * F + tx * 4) = make_float4(al[i][0], al[i][1], al[i][2], al[i][3]);
        *(float4*)(g_yr + (size_t)node * F + tx * 4) = make_float4(ar[i][0], ar[i][1], ar[i][2], ar[i][3]);
    }
}

// ---------------- aggregate + epilogue: h = relu(invdeg * sum yl[src] + yr + b) ----------------
__global__ void k_aggr(const float* __restrict__ b) {
    int warp = (blockIdx.x * blockDim.x + threadIdx.x) >> 5;
    int lane = threadIdx.x & 31;
    if (warp >= N_NODES) return;
    int s0 = g_rowptr[warp];
    int s1 = g_rowptr[warp + 1];
    float ax = 0.0f, ay = 0.0f;
    int j = s0;
    for (; j + 4 <= s1; j += 4) {
        int i0 = g_col[j + 0];
        int i1 = g_col[j + 1];
        int i2 = g_col[j + 2];
        int i3 = g_col[j + 3];
        float2 v0 = *(const float2*)(g_yl + (size_t)i0 * F + lane * 2);
        float2 v1 = *(const float2*)(g_yl + (size_t)i1 * F + lane * 2);
        float2 v2 = *(const float2*)(g_yl + (size_t)i2 * F + lane * 2);
        float2 v3 = *(const float2*)(g_yl + (size_t)i3 * F + lane * 2);
        ax += (v0.x + v1.x) + (v2.x + v3.x);
        ay += (v0.y + v1.y) + (v2.y + v3.y);
    }
    for (; j < s1; j++) {
        int i0 = g_col[j];
        float2 v0 = *(const float2*)(g_yl + (size_t)i0 * F + lane * 2);
        ax += v0.x;
        ay += v0.y;
    }
    float id = g_invdeg[warp];
    float2 r = *(const float2*)(g_yr + (size_t)warp * F + lane * 2);
    float b0 = b[lane * 2], b1 = b[lane * 2 + 1];
    float o0 = fmaxf(ax * id + r.x + b0, 0.0f);
    float o1 = fmaxf(ay * id + r.y + b1, 0.0f);
    *(float2*)(g_h + (size_t)warp * F + lane * 2) = make_float2(o0, o1);
}

// ---------------- output layer transform: 4 outputs per node ----------------
__global__ void k_transform_out(const float* __restrict__ Wlo,
                                const float* __restrict__ Wro) {
    __shared__ float sW[4 * F];
    int t = threadIdx.x;
    if (t < 128) sW[t] = Wlo[t];
    else if (t < 256) sW[t] = Wro[t - 128];
    __syncthreads();
    int i = blockIdx.x * blockDim.x + t;
    if (i >= N_NODES) return;
    const float4* hr = (const float4*)(g_h + (size_t)i * F);
    float a0 = 0, a1 = 0, r0 = 0, r1 = 0;
    #pragma unroll
    for (int q = 0; q < 16; q++) {
        float4 hv = hr[q];
        int k = q * 4;
        a0 += hv.x * sW[0 * F + k] + hv.y * sW[0 * F + k + 1] + hv.z * sW[0 * F + k + 2] + hv.w * sW[0 * F + k + 3];
        a1 += hv.x * sW[1 * F + k] + hv.y * sW[1 * F + k + 1] + hv.z * sW[1 * F + k + 2] + hv.w * sW[1 * F + k + 3];
        r0 += hv.x * sW[2 * F + k] + hv.y * sW[2 * F + k + 1] + hv.z * sW[2 * F + k + 2] + hv.w * sW[2 * F + k + 3];
        r1 += hv.x * sW[3 * F + k] + hv.y * sW[3 * F + k + 1] + hv.z * sW[3 * F + k + 2] + hv.w * sW[3 * F + k + 3];
    }
    g_y2l[i * 2 + 0] = a0;
    g_y2l[i * 2 + 1] = a1;
    g_y2r[i * 2 + 0] = r0;
    g_y2r[i * 2 + 1] = r1;
}

// ---------------- output aggregation + graph pooling accumulate ----------------
__global__ void k_aggr_out(const void* __restrict__ batch,
                           const float* __restrict__ b_out) {
    int i = blockIdx.x * blockDim.x + threadIdx.x;
    if (i >= N_NODES) return;
    int s0 = g_rowptr[i];
    int s1 = g_rowptr[i + 1];
    float a0 = 0.0f, a1 = 0.0f;
    for (int j = s0; j < s1; j++) {
        int src = g_col[j];
        float2 v = *(const float2*)(g_y2l + (size_t)src * 2);
        a0 += v.x;
        a1 += v.y;
    }
    float id = g_invdeg[i];
    float o0 = a0 * id + g_y2r[i * 2 + 0] + b_out[0];
    float o1 = a1 * id + g_y2r[i * 2 + 1] + b_out[1];
    int g = idx_at(batch, i);
    atomicAdd(&g_gsum[g * 2 + 0], o0);
    atomicAdd(&g_gsum[g * 2 + 1], o1);
}

__global__ void k_final(float* __restrict__ out) {
    int i = threadIdx.x;
    if (i < N_GRAPHS * 2) {
        int g = i >> 1;
        float c = (float)max(g_gcnt[g], 1);
        out[i] = g_gsum[i] / c;
    }
}

// ---------------- launch ----------------
extern "C" void kernel_launch(void* const* d_in, const int* in_sizes, int n_in,
                              void* d_out, int out_size) {
    const float* x      = (const float*)d_in[0];
    const void*  ei     = d_in[1];   // int64 or int32 [2, E]
    const void*  batch  = d_in[2];   // int64 or int32 [N]
    const float* Wl     = (const float*)d_in[3];   // [3,64,64]
    const float* Wr     = (const float*)d_in[4];   // [3,64,64]
    const float* b      = (const float*)d_in[5];   // [3,64]
    const float* Wl_out = (const float*)d_in[6];   // [2,64]
    const float* Wr_out = (const float*)d_in[7];   // [2,64]
    const float* b_out  = (const float*)d_in[8];   // [2]
    float*       out    = (float*)d_out;

    // dtype probe + CSR build (once per launch; graph fixed across layers)
    k_detect<<<1, 32>>>(ei);
    k_init<<<(N_NODES + 255) / 256, 256>>>();
    k_count<<<(N_EDGES + 255) / 256, 256>>>(ei, batch);
    k_scan1<<<SCAN_NB, 256>>>();
    k_scan2<<<1, 256>>>();
    k_scan3<<<SCAN_NB, 256>>>();
    k_fill<<<(N_EDGES + 255) / 256, 256>>>(ei);

    const int TGRID = N_NODES / 64;                 // 1000 blocks, 64 nodes each
    const int AGRID = (N_NODES * 32 + 255) / 256;   // warp per node

    // 3 hidden SAGEConv layers: transform-then-aggregate (aggregation commutes with Wl)
    k_transform<<<TGRID, 256>>>(x, 1, Wl + 0 * F * F, Wr + 0 * F * F);
    k_aggr<<<AGRID, 256>>>(b + 0 * F);
    k_transform<<<TGRID, 256>>>(x, 0, Wl + 1 * F * F, Wr + 1 * F * F);
    k_aggr<<<AGRID, 256>>>(b + 1 * F);
    k_transform<<<TGRID, 256>>>(x, 0, Wl + 2 * F * F, Wr + 2 * F * F);
    k_aggr<<<AGRID, 256>>>(b + 2 * F);

    // output layer + global mean pool
    k_transform_out<<<(N_NODES + 255) / 256, 256>>>(Wl_out, Wr_out);
    k_aggr_out<<<(N_NODES + 255) / 256, 256>>>(batch, b_out);
    k_final<<<1, 256>>>(out);
}

// round 4
// speedup vs baseline: 2.0452x; 1.1430x over previous
#include <cuda_runtime.h>

#define N_NODES 64000
#define N_EDGES 1024000
#define F 64
#define N_GRAPHS 128
#define SCAN_NB 250   // 250 * 256 == 64000

typedef unsigned long long u64;

// ---------------- persistent device scratch ----------------
__device__ int   g_is64;               // 1 if edge/batch indices are int64, 0 if int32
__device__ int   g_deg[N_NODES];
__device__ int   g_rowptr[N_NODES + 1];
__device__ int   g_cursor[N_NODES];
__device__ int   g_col[N_EDGES];
__device__ float g_invdeg[N_NODES];
__device__ int   g_bsum[SCAN_NB];

__device__ __align__(16) float g_yl[N_NODES * F];   // h @ Wl.T
__device__ __align__(16) float g_yr[N_NODES * F];   // h @ Wr.T
__device__ __align__(16) float g_h[N_NODES * F];    // layer output

__device__ __align__(16) float g_y2l[N_NODES * 2];
__device__ __align__(16) float g_y2r[N_NODES * 2];
__device__ float g_gsum[N_GRAPHS * 2];
__device__ int   g_gcnt[N_GRAPHS];

// flag-dispatched integer accessor (handles int64 or int32 input arrays)
__device__ __forceinline__ int idx_at(const void* p, int i) {
    if (g_is64) return (int)((const long long*)p)[i];
    return ((const int*)p)[i];
}

// ---------------- packed f32x2 helpers (sm_100a) ----------------
__device__ __forceinline__ u64 pk2(float lo, float hi) {
    u64 r; asm("mov.b64 %0,{%1,%2};" : "=l"(r) : "f"(lo), "f"(hi)); return r;
}
__device__ __forceinline__ u64 ffma2(u64 a, u64 b, u64 c) {
    u64 r; asm("fma.rn.f32x2 %0,%1,%2,%3;" : "=l"(r) : "l"(a), "l"(b), "l"(c)); return r;
}
__device__ __forceinline__ void upk2(u64 v, float& lo, float& hi) {
    asm("mov.b64 {%0,%1},%2;" : "=f"(lo), "=f"(hi) : "l"(v));
}

// ---------------- init + warp-parallel dtype probe ----------------
__global__ void k_init(const void* __restrict__ ei) {
    int i = blockIdx.x * blockDim.x + threadIdx.x;
    if (blockIdx.x == 0 && threadIdx.x < 32) {
        const long long* p = (const long long*)ei;
        long long v1 = p[threadIdx.x];
        long long v2 = p[threadIdx.x + 32];
        int bad = (v1 < 0 || v1 >= (long long)N_NODES) ||
                  (v2 < 0 || v2 >= (long long)N_NODES);
        unsigned m = __ballot_sync(0xffffffffu, bad);
        if (threadIdx.x == 0) g_is64 = (m == 0);
    }
    if (i < N_NODES) g_deg[i] = 0;
    if (i < N_GRAPHS * 2) g_gsum[i] = 0.0f;
    if (i < N_GRAPHS) g_gcnt[i] = 0;
}

// ---------------- count degrees (4 edges / thread) + graph sizes ----------------
__global__ void k_count(const void* __restrict__ ei,
                        const void* __restrict__ batch) {
    int tid = blockIdx.x * blockDim.x + threadIdx.x;
    int e4 = tid * 4;
    if (e4 < N_EDGES) {
        int d0, d1, d2, d3;
        if (g_is64) {
            const longlong2* p = (const longlong2*)((const long long*)ei + N_EDGES);
            longlong2 a = p[tid * 2], c = p[tid * 2 + 1];
            d0 = (int)a.x; d1 = (int)a.y; d2 = (int)c.x; d3 = (int)c.y;
        } else {
            int4 a = ((const int4*)((const int*)ei + N_EDGES))[tid];
            d0 = a.x; d1 = a.y; d2 = a.z; d3 = a.w;
        }
        atomicAdd(&g_deg[d0], 1);
        atomicAdd(&g_deg[d1], 1);
        atomicAdd(&g_deg[d2], 1);
        atomicAdd(&g_deg[d3], 1);
    }
    if (e4 < N_NODES) {
        int b0, b1, b2, b3;
        if (g_is64) {
            const longlong2* p = (const longlong2*)batch;
            longlong2 a = p[tid * 2], c = p[tid * 2 + 1];
            b0 = (int)a.x; b1 = (int)a.y; b2 = (int)c.x; b3 = (int)c.y;
        } else {
            int4 a = ((const int4*)batch)[tid];
            b0 = a.x; b1 = a.y; b2 = a.z; b3 = a.w;
        }
        if (b0 == b3) {   // batch sorted -> usually all 4 equal
            atomicAdd(&g_gcnt[b0], 4);
        } else {
            atomicAdd(&g_gcnt[b0], 1);
            atomicAdd(&g_gcnt[b1], 1);
            atomicAdd(&g_gcnt[b2], 1);
            atomicAdd(&g_gcnt[b3], 1);
        }
    }
}

// inclusive block scan over 256 elements (shuffle + smem)
__device__ __forceinline__ int block_scan_incl(int v) {
    int t = threadIdx.x, lane = t & 31, w = t >> 5;
    #pragma unroll
    for (int o = 1; o < 32; o <<= 1) {
        int n = __shfl_up_sync(0xffffffffu, v, o);
        if (lane >= o) v += n;
    }
    __shared__ int ws[8];
    if (lane == 31) ws[w] = v;
    __syncthreads();
    int add = 0;
    #pragma unroll
    for (int i = 0; i < 8; i++)
        if (i < w) add += ws[i];
    return v + add;
}

// phase 1: per-block sums of 256 degrees
__global__ void k_scan1() {
    int t = threadIdx.x, b = blockIdx.x;
    int v = g_deg[b * 256 + t];
    #pragma unroll
    for (int o = 16; o > 0; o >>= 1) v += __shfl_down_sync(0xffffffffu, v, o);
    __shared__ int ws[8];
    if ((t & 31) == 0) ws[t >> 5] = v;
    __syncthreads();
    if (t == 0) {
        int s = 0;
        #pragma unroll
        for (int i = 0; i < 8; i++) s += ws[i];
        g_bsum[b] = s;
    }
}

// phase 2: each block computes its own global offset from the 250 block sums,
// then block-local exclusive scan -> rowptr/cursor/invdeg
__global__ void k_scan3() {
    int t = threadIdx.x, b = blockIdx.x;
    // offset = sum of g_bsum[i] for i < b
    int v = (t < b) ? g_bsum[t] : 0;   // t < 256, b <= 249 < 250
    #pragma unroll
    for (int o = 16; o > 0; o >>= 1) v += __shfl_down_sync(0xffffffffu, v, o);
    __shared__ int ws2[8];
    __shared__ int s_off;
    if ((t & 31) == 0) ws2[t >> 5] = v;
    __syncthreads();
    if (t == 0) {
        int s = 0;
        #pragma unroll
        for (int i = 0; i < 8; i++) s += ws2[i];
        s_off = s;
    }
    // block_scan_incl's internal __syncthreads orders s_off for all threads
    int i = b * 256 + t;
    int d = g_deg[i];
    int incl = block_scan_incl(d);
    int excl = incl - d + s_off;
    g_rowptr[i] = excl;
    g_cursor[i] = excl;
    g_invdeg[i] = (d > 0) ? (1.0f / (float)d) : 0.0f;
    if (i == N_NODES - 1) g_rowptr[N_NODES] = excl + d;
}

// fill CSR columns (4 edges / thread)
__global__ void k_fill(const void* __restrict__ ei) {
    int tid = blockIdx.x * blockDim.x + threadIdx.x;
    int e4 = tid * 4;
    if (e4 >= N_EDGES) return;
    int d0, d1, d2, d3, s0, s1, s2, s3;
    if (g_is64) {
        const longlong2* pd = (const longlong2*)((const long long*)ei + N_EDGES);
        const longlong2* ps = (const longlong2*)((const long long*)ei);
        longlong2 a = pd[tid * 2], c = pd[tid * 2 + 1];
        longlong2 e = ps[tid * 2], f = ps[tid * 2 + 1];
        d0 = (int)a.x; d1 = (int)a.y; d2 = (int)c.x; d3 = (int)c.y;
        s0 = (int)e.x; s1 = (int)e.y; s2 = (int)f.x; s3 = (int)f.y;
    } else {
        int4 a = ((const int4*)((const int*)ei + N_EDGES))[tid];
        int4 e = ((const int4*)((const int*)ei))[tid];
        d0 = a.x; d1 = a.y; d2 = a.z; d3 = a.w;
        s0 = e.x; s1 = e.y; s2 = e.z; s3 = e.w;
    }
    int p0 = atomicAdd(&g_cursor[d0], 1); g_col[p0] = s0;
    int p1 = atomicAdd(&g_cursor[d1], 1); g_col[p1] = s1;
    int p2 = atomicAdd(&g_cursor[d2], 1); g_col[p2] = s2;
    int p3 = atomicAdd(&g_cursor[d3], 1); g_col[p3] = s3;
}

// ---------------- dense transform: yl = h @ Wl.T, yr = h @ Wr.T ----------------
// 16x16 threads, 64-node x 64-col tile, 4x4 register tile, packed f32x2 FMA.
__global__ void __launch_bounds__(256) k_transform(
        const float* __restrict__ x_ext, int use_x,
        const float* __restrict__ Wl,
        const float* __restrict__ Wr) {
    __shared__ float sH[F * F];    // sH[k*64 + node]
    __shared__ float sWl[F * F];   // sWl[k*64 + c] = Wl[c*64 + k]
    __shared__ float sWr[F * F];
    const float* h = use_x ? x_ext : g_h;
    int t = threadIdx.x;
    int base = blockIdx.x * 64;

    for (int idx = t; idx < F * F; idx += 256) {
        int c = idx & 63, k = idx >> 6;
        sWl[k * F + c] = Wl[c * F + k];
        sWr[k * F + c] = Wr[c * F + k];
    }
    {
        int n = t & 63, kq = t >> 6;
        const float* hrow = h + (size_t)(base + n) * F;
        #pragma unroll
        for (int j = 0; j < 4; j++) {
            int kk = (kq + j * 4) * 4;
            float4 v = *(const float4*)(hrow + kk);
            sH[(kk + 0) * F + n] = v.x;
            sH[(kk + 1) * F + n] = v.y;
            sH[(kk + 2) * F + n] = v.z;
            sH[(kk + 3) * F + n] = v.w;
        }
    }
    __syncthreads();

    int tx = t & 15, ty = t >> 4;   // col group / node group
    u64 al2[4][2], ar2[4][2];
    #pragma unroll
    for (int i = 0; i < 4; i++) {
        al2[i][0] = 0ull; al2[i][1] = 0ull;
        ar2[i][0] = 0ull; ar2[i][1] = 0ull;
    }

    #pragma unroll 8
    for (int k = 0; k < F; k++) {
        float4 a  = *(const float4*)&sH [k * F + ty * 4];
        float4 bl = *(const float4*)&sWl[k * F + tx * 4];
        float4 br = *(const float4*)&sWr[k * F + tx * 4];
        u64 b0 = pk2(bl.x, bl.y), b1 = pk2(bl.z, bl.w);
        u64 c0 = pk2(br.x, br.y), c1 = pk2(br.z, br.w);
        float av[4] = {a.x, a.y, a.z, a.w};
        #pragma unroll
        for (int i = 0; i < 4; i++) {
            u64 ai = pk2(av[i], av[i]);
            al2[i][0] = ffma2(ai, b0, al2[i][0]);
            al2[i][1] = ffma2(ai, b1, al2[i][1]);
            ar2[i][0] = ffma2(ai, c0, ar2[i][0]);
            ar2[i][1] = ffma2(ai, c1, ar2[i][1]);
        }
    }

    #pragma unroll
    for (int i = 0; i < 4; i++) {
        int node = base + ty * 4 + i;
        float l0, l1, l2, l3, r0, r1, r2, r3;
        upk2(al2[i][0], l0, l1); upk2(al2[i][1], l2, l3);
        upk2(ar2[i][0], r0, r1); upk2(ar2[i][1], r2, r3);
        *(float4*)(g_yl + (size_t)node * F + tx * 4) = make_float4(l0, l1, l2, l3);
        *(float4*)(g_yr + (size_t)node * F + tx * 4) = make_float4(r0, r1, r2, r3);
    }
}

// ---------------- aggregate + epilogue: h = relu(invdeg * sum yl[src] + yr + b) ----------------
__global__ void k_aggr(const float* __restrict__ b) {
    int warp = (blockIdx.x * blockDim.x + threadIdx.x) >> 5;
    int lane = threadIdx.x & 31;
    if (warp >= N_NODES) return;
    int s0 = g_rowptr[warp];
    int s1 = g_rowptr[warp + 1];
    float ax = 0.0f, ay = 0.0f;
    int j = s0;
    for (; j + 8 <= s1; j += 8) {
        int i0 = g_col[j + 0], i1 = g_col[j + 1], i2 = g_col[j + 2], i3 = g_col[j + 3];
        int i4 = g_col[j + 4], i5 = g_col[j + 5], i6 = g_col[j + 6], i7 = g_col[j + 7];
        float2 v0 = *(const float2*)(g_yl + (size_t)i0 * F + lane * 2);
        float2 v1 = *(const float2*)(g_yl + (size_t)i1 * F + lane * 2);
        float2 v2 = *(const float2*)(g_yl + (size_t)i2 * F + lane * 2);
        float2 v3 = *(const float2*)(g_yl + (size_t)i3 * F + lane * 2);
        float2 v4 = *(const float2*)(g_yl + (size_t)i4 * F + lane * 2);
        float2 v5 = *(const float2*)(g_yl + (size_t)i5 * F + lane * 2);
        float2 v6 = *(const float2*)(g_yl + (size_t)i6 * F + lane * 2);
        float2 v7 = *(const float2*)(g_yl + (size_t)i7 * F + lane * 2);
        ax += ((v0.x + v1.x) + (v2.x + v3.x)) + ((v4.x + v5.x) + (v6.x + v7.x));
        ay += ((v0.y + v1.y) + (v2.y + v3.y)) + ((v4.y + v5.y) + (v6.y + v7.y));
    }
    for (; j + 2 <= s1; j += 2) {
        int i0 = g_col[j], i1 = g_col[j + 1];
        float2 v0 = *(const float2*)(g_yl + (size_t)i0 * F + lane * 2);
        float2 v1 = *(const float2*)(g_yl + (size_t)i1 * F + lane * 2);
        ax += v0.x + v1.x;
        ay += v0.y + v1.y;
    }
    if (j < s1) {
        int i0 = g_col[j];
        float2 v0 = *(const float2*)(g_yl + (size_t)i0 * F + lane * 2);
        ax += v0.x;
        ay += v0.y;
    }
    float id = g_invdeg[warp];
    float2 r = *(const float2*)(g_yr + (size_t)warp * F + lane * 2);
    float b0 = b[lane * 2], b1 = b[lane * 2 + 1];
    float o0 = fmaxf(ax * id + r.x + b0, 0.0f);
    float o1 = fmaxf(ay * id + r.y + b1, 0.0f);
    *(float2*)(g_h + (size_t)warp * F + lane * 2) = make_float2(o0, o1);
}

// ---------------- output layer transform: 4 outputs per node ----------------
__global__ void k_transform_out(const float* __restrict__ Wlo,
                                const float* __restrict__ Wro) {
    __shared__ float sW[4 * F];
    int t = threadIdx.x;
    if (t < 128) sW[t] = Wlo[t];
    else if (t < 256) sW[t] = Wro[t - 128];
    __syncthreads();
    int i = blockIdx.x * blockDim.x + t;
    if (i >= N_NODES) return;
    const float4* hr = (const float4*)(g_h + (size_t)i * F);
    float a0 = 0, a1 = 0, r0 = 0, r1 = 0;
    #pragma unroll
    for (int q = 0; q < 16; q++) {
        float4 hv = hr[q];
        int k = q * 4;
        a0 += hv.x * sW[0 * F + k] + hv.y * sW[0 * F + k + 1] + hv.z * sW[0 * F + k + 2] + hv.w * sW[0 * F + k + 3];
        a1 += hv.x * sW[1 * F + k] + hv.y * sW[1 * F + k + 1] + hv.z * sW[1 * F + k + 2] + hv.w * sW[1 * F + k + 3];
        r0 += hv.x * sW[2 * F + k] + hv.y * sW[2 * F + k + 1] + hv.z * sW[2 * F + k + 2] + hv.w * sW[2 * F + k + 3];
        r1 += hv.x * sW[3 * F + k] + hv.y * sW[3 * F + k + 1] + hv.z * sW[3 * F + k + 2] + hv.w * sW[3 * F + k + 3];
    }
    g_y2l[i * 2 + 0] = a0;
    g_y2l[i * 2 + 1] = a1;
    g_y2r[i * 2 + 0] = r0;
    g_y2r[i * 2 + 1] = r1;
}

// ---------------- output aggregation + graph pooling accumulate ----------------
__global__ void k_aggr_out(const void* __restrict__ batch,
                           const float* __restrict__ b_out) {
    int i = blockIdx.x * blockDim.x + threadIdx.x;
    if (i >= N_NODES) return;
    int s0 = g_rowptr[i];
    int s1 = g_rowptr[i + 1];
    float a0 = 0.0f, a1 = 0.0f;
    for (int j = s0; j < s1; j++) {
        int src = g_col[j];
        float2 v = *(const float2*)(g_y2l + (size_t)src * 2);
        a0 += v.x;
        a1 += v.y;
    }
    float id = g_invdeg[i];
    float o0 = a0 * id + g_y2r[i * 2 + 0] + b_out[0];
    float o1 = a1 * id + g_y2r[i * 2 + 1] + b_out[1];
    int g = idx_at(batch, i);
    atomicAdd(&g_gsum[g * 2 + 0], o0);
    atomicAdd(&g_gsum[g * 2 + 1], o1);
}

__global__ void k_final(float* __restrict__ out) {
    int i = threadIdx.x;
    if (i < N_GRAPHS * 2) {
        int g = i >> 1;
        float c = (float)max(g_gcnt[g], 1);
        out[i] = g_gsum[i] / c;
    }
}

// ---------------- launch ----------------
extern "C" void kernel_launch(void* const* d_in, const int* in_sizes, int n_in,
                              void* d_out, int out_size) {
    const float* x      = (const float*)d_in[0];
    const void*  ei     = d_in[1];   // int64 or int32 [2, E]
    const void*  batch  = d_in[2];   // int64 or int32 [N]
    const float* Wl     = (const float*)d_in[3];   // [3,64,64]
    const float* Wr     = (const float*)d_in[4];   // [3,64,64]
    const float* b      = (const float*)d_in[5];   // [3,64]
    const float* Wl_out = (const float*)d_in[6];   // [2,64]
    const float* Wr_out = (const float*)d_in[7];   // [2,64]
    const float* b_out  = (const float*)d_in[8];   // [2]
    float*       out    = (float*)d_out;

    // CSR build (probe folded into init; scan2 folded into scan3)
    k_init<<<SCAN_NB, 256>>>(ei);                      // launch 0
    k_count<<<N_EDGES / 4 / 256, 256>>>(ei, batch);    // launch 1
    k_scan1<<<SCAN_NB, 256>>>();                       // launch 2
    k_scan3<<<SCAN_NB, 256>>>();                       // launch 3
    k_fill<<<N_EDGES / 4 / 256, 256>>>(ei);            // launch 4

    const int TGRID = N_NODES / 64;                 // 1000 blocks, 64 nodes each
    const int AGRID = (N_NODES * 32 + 255) / 256;   // warp per node

    // 3 hidden SAGEConv layers (launch 5 = k_transform -> profiled next round)
    k_transform<<<TGRID, 256>>>(x, 1, Wl + 0 * F * F, Wr + 0 * F * F);
    k_aggr<<<AGRID, 256>>>(b + 0 * F);
    k_transform<<<TGRID, 256>>>(x, 0, Wl + 1 * F * F, Wr + 1 * F * F);
    k_aggr<<<AGRID, 256>>>(b + 1 * F);
    k_transform<<<TGRID, 256>>>(x, 0, Wl + 2 * F * F, Wr + 2 * F * F);
    k_aggr<<<AGRID, 256>>>(b + 2 * F);

    // output layer + global mean pool
    k_transform_out<<<(N_NODES + 255) / 256, 256>>>(Wl_out, Wr_out);
    k_aggr_out<<<(N_NODES + 255) / 256, 256>>>(batch, b_out);
    k_final<<<1, 256>>>(out);
}

// round 5
// speedup vs baseline: 2.1094x; 1.0314x over previous
#include <cuda_runtime.h>

#define N_NODES 64000
#define N_EDGES 1024000
#define F 64
#define N_GRAPHS 128
#define SCAN_NB 250   // 250 * 256 == 64000

typedef unsigned long long u64;

// ---------------- persistent device scratch ----------------
__device__ int   g_is64;               // 1 if edge/batch indices are int64, 0 if int32
__device__ int   g_deg[N_NODES];
__device__ int   g_rowptr[N_NODES + 1];
__device__ int   g_cursor[N_NODES];
__device__ int   g_col[N_EDGES];
__device__ float g_invdeg[N_NODES];

__device__ __align__(16) float g_yl[N_NODES * F];   // h @ Wl.T
__device__ __align__(16) float g_yr[N_NODES * F];   // h @ Wr.T
__device__ __align__(16) float g_h[N_NODES * F];    // layer output

__device__ __align__(16) float g_y2l[N_NODES * 2];
__device__ __align__(16) float g_y2r[N_NODES * 2];
__device__ float g_gsum[N_GRAPHS * 2];
__device__ int   g_gcnt[N_GRAPHS];

// flag-dispatched integer accessor (handles int64 or int32 input arrays)
__device__ __forceinline__ int idx_at(const void* p, int i) {
    if (g_is64) return (int)((const long long*)p)[i];
    return ((const int*)p)[i];
}

// ---------------- packed f32x2 helpers (sm_100a) ----------------
__device__ __forceinline__ u64 pk2(float lo, float hi) {
    u64 r; asm("mov.b64 %0,{%1,%2};" : "=l"(r) : "f"(lo), "f"(hi)); return r;
}
__device__ __forceinline__ u64 ffma2(u64 a, u64 b, u64 c) {
    u64 r; asm("fma.rn.f32x2 %0,%1,%2,%3;" : "=l"(r) : "l"(a), "l"(b), "l"(c)); return r;
}
__device__ __forceinline__ void upk2(u64 v, float& lo, float& hi) {
    asm("mov.b64 {%0,%1},%2;" : "=f"(lo), "=f"(hi) : "l"(v));
}

// ---------------- init + warp-parallel dtype probe ----------------
__global__ void k_init(const void* __restrict__ ei) {
    int i = blockIdx.x * blockDim.x + threadIdx.x;
    if (blockIdx.x == 0 && threadIdx.x < 32) {
        const long long* p = (const long long*)ei;
        long long v1 = p[threadIdx.x];
        long long v2 = p[threadIdx.x + 32];
        int bad = (v1 < 0 || v1 >= (long long)N_NODES) ||
                  (v2 < 0 || v2 >= (long long)N_NODES);
        unsigned m = __ballot_sync(0xffffffffu, bad);
        if (threadIdx.x == 0) g_is64 = (m == 0);
    }
    if (i < N_NODES) g_deg[i] = 0;
    if (i < N_GRAPHS * 2) g_gsum[i] = 0.0f;
    if (i < N_GRAPHS) g_gcnt[i] = 0;
}

// ---------------- count degrees (4 edges / thread) + graph sizes ----------------
__global__ void k_count(const void* __restrict__ ei,
                        const void* __restrict__ batch) {
    int tid = blockIdx.x * blockDim.x + threadIdx.x;
    int e4 = tid * 4;
    if (e4 < N_EDGES) {
        int d0, d1, d2, d3;
        if (g_is64) {
            const longlong2* p = (const longlong2*)((const long long*)ei + N_EDGES);
            longlong2 a = p[tid * 2], c = p[tid * 2 + 1];
            d0 = (int)a.x; d1 = (int)a.y; d2 = (int)c.x; d3 = (int)c.y;
        } else {
            int4 a = ((const int4*)((const int*)ei + N_EDGES))[tid];
            d0 = a.x; d1 = a.y; d2 = a.z; d3 = a.w;
        }
        atomicAdd(&g_deg[d0], 1);
        atomicAdd(&g_deg[d1], 1);
        atomicAdd(&g_deg[d2], 1);
        atomicAdd(&g_deg[d3], 1);
    }
    if (e4 < N_NODES) {
        int b0, b1, b2, b3;
        if (g_is64) {
            const longlong2* p = (const longlong2*)batch;
            longlong2 a = p[tid * 2], c = p[tid * 2 + 1];
            b0 = (int)a.x; b1 = (int)a.y; b2 = (int)c.x; b3 = (int)c.y;
        } else {
            int4 a = ((const int4*)batch)[tid];
            b0 = a.x; b1 = a.y; b2 = a.z; b3 = a.w;
        }
        if (b0 == b3) {
            atomicAdd(&g_gcnt[b0], 4);
        } else {
            atomicAdd(&g_gcnt[b0], 1);
            atomicAdd(&g_gcnt[b1], 1);
            atomicAdd(&g_gcnt[b2], 1);
            atomicAdd(&g_gcnt[b3], 1);
        }
    }
}

// inclusive block scan over 256 elements (shuffle + smem)
__device__ __forceinline__ int block_scan_incl(int v) {
    int t = threadIdx.x, lane = t & 31, w = t >> 5;
    #pragma unroll
    for (int o = 1; o < 32; o <<= 1) {
        int n = __shfl_up_sync(0xffffffffu, v, o);
        if (lane >= o) v += n;
    }
    __shared__ int ws[8];
    if (lane == 31) ws[w] = v;
    __syncthreads();
    int add = 0;
    #pragma unroll
    for (int i = 0; i < 8; i++)
        if (i < w) add += ws[i];
    return v + add;
}

// merged scan: each block computes its global offset from g_deg directly,
// then block-local exclusive scan -> rowptr/cursor/invdeg
__global__ void k_scan() {
    int t = threadIdx.x, b = blockIdx.x;
    // partial sum of g_deg[0 .. 256*b), strided partition
    int off = 0;
    int lim = b * 256;
    for (int i = t; i < lim; i += 256) off += g_deg[i];
    // reduce across block
    #pragma unroll
    for (int o = 16; o > 0; o >>= 1) off += __shfl_down_sync(0xffffffffu, off, o);
    __shared__ int ws2[8];
    __shared__ int s_off;
    if ((t & 31) == 0) ws2[t >> 5] = off;
    __syncthreads();
    if (t == 0) {
        int s = 0;
        #pragma unroll
        for (int i = 0; i < 8; i++) s += ws2[i];
        s_off = s;
    }
    // block_scan_incl's internal __syncthreads orders s_off for all threads
    int i = b * 256 + t;
    int d = g_deg[i];
    int incl = block_scan_incl(d);
    int excl = incl - d + s_off;
    g_rowptr[i] = excl;
    g_cursor[i] = excl;
    g_invdeg[i] = (d > 0) ? (1.0f / (float)d) : 0.0f;
    if (i == N_NODES - 1) g_rowptr[N_NODES] = excl + d;
}

// fill CSR columns (4 edges / thread)
__global__ void k_fill(const void* __restrict__ ei) {
    int tid = blockIdx.x * blockDim.x + threadIdx.x;
    int e4 = tid * 4;
    if (e4 >= N_EDGES) return;
    int d0, d1, d2, d3, s0, s1, s2, s3;
    if (g_is64) {
        const longlong2* pd = (const longlong2*)((const long long*)ei + N_EDGES);
        const longlong2* ps = (const longlong2*)((const long long*)ei);
        longlong2 a = pd[tid * 2], c = pd[tid * 2 + 1];
        longlong2 e = ps[tid * 2], f = ps[tid * 2 + 1];
        d0 = (int)a.x; d1 = (int)a.y; d2 = (int)c.x; d3 = (int)c.y;
        s0 = (int)e.x; s1 = (int)e.y; s2 = (int)f.x; s3 = (int)f.y;
    } else {
        int4 a = ((const int4*)((const int*)ei + N_EDGES))[tid];
        int4 e = ((const int4*)((const int*)ei))[tid];
        d0 = a.x; d1 = a.y; d2 = a.z; d3 = a.w;
        s0 = e.x; s1 = e.y; s2 = e.z; s3 = e.w;
    }
    int p0 = atomicAdd(&g_cursor[d0], 1); g_col[p0] = s0;
    int p1 = atomicAdd(&g_cursor[d1], 1); g_col[p1] = s1;
    int p2 = atomicAdd(&g_cursor[d2], 1); g_col[p2] = s2;
    int p3 = atomicAdd(&g_cursor[d3], 1); g_col[p3] = s3;
}

// ---------------- dense transform: yl = h @ Wl.T, yr = h @ Wr.T ----------------
__global__ void __launch_bounds__(256) k_transform(
        const float* __restrict__ x_ext, int use_x,
        const float* __restrict__ Wl,
        const float* __restrict__ Wr) {
    __shared__ float sH[F * F];    // sH[k*64 + node]
    __shared__ float sWl[F * F];   // sWl[k*64 + c] = Wl[c*64 + k]
    __shared__ float sWr[F * F];
    const float* h = use_x ? x_ext : g_h;
    int t = threadIdx.x;
    int base = blockIdx.x * 64;

    for (int idx = t; idx < F * F; idx += 256) {
        int c = idx & 63, k = idx >> 6;
        sWl[k * F + c] = Wl[c * F + k];
        sWr[k * F + c] = Wr[c * F + k];
    }
    {
        int n = t & 63, kq = t >> 6;
        const float* hrow = h + (size_t)(base + n) * F;
        #pragma unroll
        for (int j = 0; j < 4; j++) {
            int kk = (kq + j * 4) * 4;
            float4 v = *(const float4*)(hrow + kk);
            sH[(kk + 0) * F + n] = v.x;
            sH[(kk + 1) * F + n] = v.y;
            sH[(kk + 2) * F + n] = v.z;
            sH[(kk + 3) * F + n] = v.w;
        }
    }
    __syncthreads();

    int tx = t & 15, ty = t >> 4;
    u64 al2[4][2], ar2[4][2];
    #pragma unroll
    for (int i = 0; i < 4; i++) {
        al2[i][0] = 0ull; al2[i][1] = 0ull;
        ar2[i][0] = 0ull; ar2[i][1] = 0ull;
    }

    #pragma unroll 8
    for (int k = 0; k < F; k++) {
        float4 a  = *(const float4*)&sH [k * F + ty * 4];
        float4 bl = *(const float4*)&sWl[k * F + tx * 4];
        float4 br = *(const float4*)&sWr[k * F + tx * 4];
        u64 b0 = pk2(bl.x, bl.y), b1 = pk2(bl.z, bl.w);
        u64 c0 = pk2(br.x, br.y), c1 = pk2(br.z, br.w);
        float av[4] = {a.x, a.y, a.z, a.w};
        #pragma unroll
        for (int i = 0; i < 4; i++) {
            u64 ai = pk2(av[i], av[i]);
            al2[i][0] = ffma2(ai, b0, al2[i][0]);
            al2[i][1] = ffma2(ai, b1, al2[i][1]);
            ar2[i][0] = ffma2(ai, c0, ar2[i][0]);
            ar2[i][1] = ffma2(ai, c1, ar2[i][1]);
        }
    }

    #pragma unroll
    for (int i = 0; i < 4; i++) {
        int node = base + ty * 4 + i;
        float l0, l1, l2, l3, r0, r1, r2, r3;
        upk2(al2[i][0], l0, l1); upk2(al2[i][1], l2, l3);
        upk2(ar2[i][0], r0, r1); upk2(ar2[i][1], r2, r3);
        *(float4*)(g_yl + (size_t)node * F + tx * 4) = make_float4(l0, l1, l2, l3);
        *(float4*)(g_yr + (size_t)node * F + tx * 4) = make_float4(r0, r1, r2, r3);
    }
}

// ---------------- aggregate + epilogue ----------------
// h = relu(invdeg * sum yl[src] + yr + b)
// fuse_out: also compute y2l = h@Wlo.T, y2r = h@Wro.T via warp reduction and
//           skip the g_h store (h not needed afterwards).
__global__ void k_aggr(const float* __restrict__ b,
                       const float* __restrict__ Wlo,
                       const float* __restrict__ Wro,
                       int fuse_out) {
    __shared__ float sw[4 * F];   // Wlo row0, Wlo row1, Wro row0, Wro row1
    if (fuse_out) {
        int t = threadIdx.x;
        if (t < 128) sw[t] = Wlo[t];
        else if (t < 256) sw[t] = Wro[t - 128];
        __syncthreads();
    }
    int warp = (blockIdx.x * blockDim.x + threadIdx.x) >> 5;
    int lane = threadIdx.x & 31;
    if (warp >= N_NODES) return;
    int s0 = g_rowptr[warp];
    int s1 = g_rowptr[warp + 1];
    float ax = 0.0f, ay = 0.0f;
    int j = s0;
    for (; j + 8 <= s1; j += 8) {
        int i0 = g_col[j + 0], i1 = g_col[j + 1], i2 = g_col[j + 2], i3 = g_col[j + 3];
        int i4 = g_col[j + 4], i5 = g_col[j + 5], i6 = g_col[j + 6], i7 = g_col[j + 7];
        float2 v0 = *(const float2*)(g_yl + (size_t)i0 * F + lane * 2);
        float2 v1 = *(const float2*)(g_yl + (size_t)i1 * F + lane * 2);
        float2 v2 = *(const float2*)(g_yl + (size_t)i2 * F + lane * 2);
        float2 v3 = *(const float2*)(g_yl + (size_t)i3 * F + lane * 2);
        float2 v4 = *(const float2*)(g_yl + (size_t)i4 * F + lane * 2);
        float2 v5 = *(const float2*)(g_yl + (size_t)i5 * F + lane * 2);
        float2 v6 = *(const float2*)(g_yl + (size_t)i6 * F + lane * 2);
        float2 v7 = *(const float2*)(g_yl + (size_t)i7 * F + lane * 2);
        ax += ((v0.x + v1.x) + (v2.x + v3.x)) + ((v4.x + v5.x) + (v6.x + v7.x));
        ay += ((v0.y + v1.y) + (v2.y + v3.y)) + ((v4.y + v5.y) + (v6.y + v7.y));
    }
    for (; j + 2 <= s1; j += 2) {
        int i0 = g_col[j], i1 = g_col[j + 1];
        float2 v0 = *(const float2*)(g_yl + (size_t)i0 * F + lane * 2);
        float2 v1 = *(const float2*)(g_yl + (size_t)i1 * F + lane * 2);
        ax += v0.x + v1.x;
        ay += v0.y + v1.y;
    }
    if (j < s1) {
        int i0 = g_col[j];
        float2 v0 = *(const float2*)(g_yl + (size_t)i0 * F + lane * 2);
        ax += v0.x;
        ay += v0.y;
    }
    float id = g_invdeg[warp];
    float2 r = *(const float2*)(g_yr + (size_t)warp * F + lane * 2);
    float b0 = b[lane * 2], b1 = b[lane * 2 + 1];
    float o0 = fmaxf(ax * id + r.x + b0, 0.0f);
    float o1 = fmaxf(ay * id + r.y + b1, 0.0f);
    if (!fuse_out) {
        *(float2*)(g_h + (size_t)warp * F + lane * 2) = make_float2(o0, o1);
    } else {
        // output-layer transform fused: 4 warp-wide dot products over 64 features
        float p0 = o0 * sw[0 * F + lane * 2] + o1 * sw[0 * F + lane * 2 + 1];
        float p1 = o0 * sw[1 * F + lane * 2] + o1 * sw[1 * F + lane * 2 + 1];
        float p2 = o0 * sw[2 * F + lane * 2] + o1 * sw[2 * F + lane * 2 + 1];
        float p3 = o0 * sw[3 * F + lane * 2] + o1 * sw[3 * F + lane * 2 + 1];
        #pragma unroll
        for (int o = 16; o > 0; o >>= 1) {
            p0 += __shfl_xor_sync(0xffffffffu, p0, o);
            p1 += __shfl_xor_sync(0xffffffffu, p1, o);
            p2 += __shfl_xor_sync(0xffffffffu, p2, o);
            p3 += __shfl_xor_sync(0xffffffffu, p3, o);
        }
        if (lane == 0) {
            *(float2*)(g_y2l + (size_t)warp * 2) = make_float2(p0, p1);
            *(float2*)(g_y2r + (size_t)warp * 2) = make_float2(p2, p3);
        }
    }
}

// ---------------- output aggregation + graph pooling accumulate ----------------
__global__ void k_aggr_out(const void* __restrict__ batch,
                           const float* __restrict__ b_out) {
    int i = blockIdx.x * blockDim.x + threadIdx.x;
    if (i >= N_NODES) return;
    int s0 = g_rowptr[i];
    int s1 = g_rowptr[i + 1];
    float a0 = 0.0f, a1 = 0.0f;
    for (int j = s0; j < s1; j++) {
        int src = g_col[j];
        float2 v = *(const float2*)(g_y2l + (size_t)src * 2);
        a0 += v.x;
        a1 += v.y;
    }
    float id = g_invdeg[i];
    float o0 = a0 * id + g_y2r[i * 2 + 0] + b_out[0];
    float o1 = a1 * id + g_y2r[i * 2 + 1] + b_out[1];
    int g = idx_at(batch, i);
    atomicAdd(&g_gsum[g * 2 + 0], o0);
    atomicAdd(&g_gsum[g * 2 + 1], o1);
}

__global__ void k_final(float* __restrict__ out) {
    int i = threadIdx.x;
    if (i < N_GRAPHS * 2) {
        int g = i >> 1;
        float c = (float)max(g_gcnt[g], 1);
        out[i] = g_gsum[i] / c;
    }
}

// ---------------- launch ----------------
extern "C" void kernel_launch(void* const* d_in, const int* in_sizes, int n_in,
                              void* d_out, int out_size) {
    const float* x      = (const float*)d_in[0];
    const void*  ei     = d_in[1];   // int64 or int32 [2, E]
    const void*  batch  = d_in[2];   // int64 or int32 [N]
    const float* Wl     = (const float*)d_in[3];   // [3,64,64]
    const float* Wr     = (const float*)d_in[4];   // [3,64,64]
    const float* b      = (const float*)d_in[5];   // [3,64]
    const float* Wl_out = (const float*)d_in[6];   // [2,64]
    const float* Wr_out = (const float*)d_in[7];   // [2,64]
    const float* b_out  = (const float*)d_in[8];   // [2]
    float*       out    = (float*)d_out;

    // lazy one-time host resources (created on the uncaptured correctness run)
    static cudaStream_t s2 = 0;
    static cudaEvent_t ev0 = 0, ev1 = 0;
    if (s2 == 0) {
        cudaStreamCreateWithFlags(&s2, cudaStreamNonBlocking);
        cudaEventCreateWithFlags(&ev0, cudaEventDisableTiming);
        cudaEventCreateWithFlags(&ev1, cudaEventDisableTiming);
    }

    const int TGRID = N_NODES / 64;                 // 1000 blocks, 64 nodes each
    const int AGRID = (N_NODES * 32 + 255) / 256;   // warp per node

    // fork: transform layer 0 (depends only on x/Wl0/Wr0) runs concurrently
    // with the CSR build on the main stream.
    cudaEventRecord(ev0, 0);
    cudaStreamWaitEvent(s2, ev0, 0);
    k_transform<<<TGRID, 256, 0, s2>>>(x, 1, Wl + 0 * F * F, Wr + 0 * F * F);
    cudaEventRecord(ev1, s2);

    // CSR build chain on main stream
    k_init<<<SCAN_NB, 256>>>(ei);
    k_count<<<N_EDGES / 4 / 256, 256>>>(ei, batch);
    k_scan<<<SCAN_NB, 256>>>();
    k_fill<<<N_EDGES / 4 / 256, 256>>>(ei);

    // join: aggregation layer 0 needs both CSR and transform0
    cudaStreamWaitEvent(0, ev1, 0);

    k_aggr<<<AGRID, 256>>>(b + 0 * F, Wl_out, Wr_out, 0);
    k_transform<<<TGRID, 256>>>(x, 0, Wl + 1 * F * F, Wr + 1 * F * F);
    k_aggr<<<AGRID, 256>>>(b + 1 * F, Wl_out, Wr_out, 0);
    k_transform<<<TGRID, 256>>>(x, 0, Wl + 2 * F * F, Wr + 2 * F * F);
    // layer 2: output-layer transform fused into the epilogue
    k_aggr<<<AGRID, 256>>>(b + 2 * F, Wl_out, Wr_out, 1);

    // output aggregation + global mean pool
    k_aggr_out<<<(N_NODES + 255) / 256, 256>>>(batch, b_out);
    k_final<<<1, 256>>>(out);
}

// round 6
// speedup vs baseline: 2.1425x; 1.0157x over previous
#include <cuda_runtime.h>
#include <cuda_fp16.h>

#define N_NODES 64000
#define N_EDGES 1024000
#define F 64
#define N_GRAPHS 128
#define SCAN_NB 250   // 250 * 256 == 64000

typedef unsigned long long u64;

// ---------------- persistent device scratch ----------------
__device__ int   g_is64;               // 1 if edge/batch indices are int64, 0 if int32
__device__ int   g_deg[N_NODES];
__device__ int   g_rowptr[N_NODES + 1];
__device__ int   g_cursor[N_NODES];
__device__ int   g_col[N_EDGES];
__device__ float g_invdeg[N_NODES];
__device__ int   g_bsum[SCAN_NB];

__device__ __align__(16) __half g_ylh[N_NODES * F];  // h @ Wl.T  (fp16, gathered)
__device__ __align__(16) float  g_yr[N_NODES * F];   // h @ Wr.T  (fp32, streamed)
__device__ __align__(16) float  g_h[N_NODES * F];    // layer output

__device__ __align__(16) float g_y2l[N_NODES * 2];
__device__ __align__(16) float g_y2r[N_NODES * 2];
__device__ float g_gsum[N_GRAPHS * 2];
__device__ int   g_gcnt[N_GRAPHS];

// flag-dispatched integer accessor (handles int64 or int32 input arrays)
__device__ __forceinline__ int idx_at(const void* p, int i) {
    if (g_is64) return (int)((const long long*)p)[i];
    return ((const int*)p)[i];
}

// ---------------- packed f32x2 helpers (sm_100a) ----------------
__device__ __forceinline__ u64 pk2(float lo, float hi) {
    u64 r; asm("mov.b64 %0,{%1,%2};" : "=l"(r) : "f"(lo), "f"(hi)); return r;
}
__device__ __forceinline__ u64 ffma2(u64 a, u64 b, u64 c) {
    u64 r; asm("fma.rn.f32x2 %0,%1,%2,%3;" : "=l"(r) : "l"(a), "l"(b), "l"(c)); return r;
}
__device__ __forceinline__ void upk2(u64 v, float& lo, float& hi) {
    asm("mov.b64 {%0,%1},%2;" : "=f"(lo), "=f"(hi) : "l"(v));
}

// ---------------- init + warp-parallel dtype probe ----------------
__global__ void k_init(const void* __restrict__ ei) {
    int i = blockIdx.x * blockDim.x + threadIdx.x;
    if (blockIdx.x == 0 && threadIdx.x < 32) {
        const long long* p = (const long long*)ei;
        long long v1 = p[threadIdx.x];
        long long v2 = p[threadIdx.x + 32];
        int bad = (v1 < 0 || v1 >= (long long)N_NODES) ||
                  (v2 < 0 || v2 >= (long long)N_NODES);
        unsigned m = __ballot_sync(0xffffffffu, bad);
        if (threadIdx.x == 0) g_is64 = (m == 0);
    }
    if (i < N_NODES) g_deg[i] = 0;
    if (i < N_GRAPHS * 2) g_gsum[i] = 0.0f;
    if (i < N_GRAPHS) g_gcnt[i] = 0;
}

// ---------------- count degrees (4 edges / thread) + graph sizes ----------------
__global__ void k_count(const void* __restrict__ ei,
                        const void* __restrict__ batch) {
    int tid = blockIdx.x * blockDim.x + threadIdx.x;
    int e4 = tid * 4;
    if (e4 < N_EDGES) {
        int d0, d1, d2, d3;
        if (g_is64) {
            const longlong2* p = (const longlong2*)((const long long*)ei + N_EDGES);
            longlong2 a = p[tid * 2], c = p[tid * 2 + 1];
            d0 = (int)a.x; d1 = (int)a.y; d2 = (int)c.x; d3 = (int)c.y;
        } else {
            int4 a = ((const int4*)((const int*)ei + N_EDGES))[tid];
            d0 = a.x; d1 = a.y; d2 = a.z; d3 = a.w;
        }
        atomicAdd(&g_deg[d0], 1);
        atomicAdd(&g_deg[d1], 1);
        atomicAdd(&g_deg[d2], 1);
        atomicAdd(&g_deg[d3], 1);
    }
    if (e4 < N_NODES) {
        int b0, b1, b2, b3;
        if (g_is64) {
            const longlong2* p = (const longlong2*)batch;
            longlong2 a = p[tid * 2], c = p[tid * 2 + 1];
            b0 = (int)a.x; b1 = (int)a.y; b2 = (int)c.x; b3 = (int)c.y;
        } else {
            int4 a = ((const int4*)batch)[tid];
            b0 = a.x; b1 = a.y; b2 = a.z; b3 = a.w;
        }
        if (b0 == b3) {
            atomicAdd(&g_gcnt[b0], 4);
        } else {
            atomicAdd(&g_gcnt[b0], 1);
            atomicAdd(&g_gcnt[b1], 1);
            atomicAdd(&g_gcnt[b2], 1);
            atomicAdd(&g_gcnt[b3], 1);
        }
    }
}

// inclusive block scan over 256 elements (shuffle + smem)
__device__ __forceinline__ int block_scan_incl(int v) {
    int t = threadIdx.x, lane = t & 31, w = t >> 5;
    #pragma unroll
    for (int o = 1; o < 32; o <<= 1) {
        int n = __shfl_up_sync(0xffffffffu, v, o);
        if (lane >= o) v += n;
    }
    __shared__ int ws[8];
    if (lane == 31) ws[w] = v;
    __syncthreads();
    int add = 0;
    #pragma unroll
    for (int i = 0; i < 8; i++)
        if (i < w) add += ws[i];
    return v + add;
}

// phase 1: per-block sums of 256 degrees
__global__ void k_scan1() {
    int t = threadIdx.x, b = blockIdx.x;
    int v = g_deg[b * 256 + t];
    #pragma unroll
    for (int o = 16; o > 0; o >>= 1) v += __shfl_down_sync(0xffffffffu, v, o);
    __shared__ int ws[8];
    if ((t & 31) == 0) ws[t >> 5] = v;
    __syncthreads();
    if (t == 0) {
        int s = 0;
        #pragma unroll
        for (int i = 0; i < 8; i++) s += ws[i];
        g_bsum[b] = s;
    }
}

// phase 2: block offset from the 250 block sums + block-local exclusive scan
__global__ void k_scan3() {
    int t = threadIdx.x, b = blockIdx.x;
    int v = (t < b) ? g_bsum[t] : 0;   // t < 256, b <= 249 < 250
    #pragma unroll
    for (int o = 16; o > 0; o >>= 1) v += __shfl_down_sync(0xffffffffu, v, o);
    __shared__ int ws2[8];
    __shared__ int s_off;
    if ((t & 31) == 0) ws2[t >> 5] = v;
    __syncthreads();
    if (t == 0) {
        int s = 0;
        #pragma unroll
        for (int i = 0; i < 8; i++) s += ws2[i];
        s_off = s;
    }
    // block_scan_incl's internal __syncthreads orders s_off for all threads
    int i = b * 256 + t;
    int d = g_deg[i];
    int incl = block_scan_incl(d);
    int excl = incl - d + s_off;
    g_rowptr[i] = excl;
    g_cursor[i] = excl;
    g_invdeg[i] = (d > 0) ? (1.0f / (float)d) : 0.0f;
    if (i == N_NODES - 1) g_rowptr[N_NODES] = excl + d;
}

// fill CSR columns (4 edges / thread)
__global__ void k_fill(const void* __restrict__ ei) {
    int tid = blockIdx.x * blockDim.x + threadIdx.x;
    int e4 = tid * 4;
    if (e4 >= N_EDGES) return;
    int d0, d1, d2, d3, s0, s1, s2, s3;
    if (g_is64) {
        const longlong2* pd = (const longlong2*)((const long long*)ei + N_EDGES);
        const longlong2* ps = (const longlong2*)((const long long*)ei);
        longlong2 a = pd[tid * 2], c = pd[tid * 2 + 1];
        longlong2 e = ps[tid * 2], f = ps[tid * 2 + 1];
        d0 = (int)a.x; d1 = (int)a.y; d2 = (int)c.x; d3 = (int)c.y;
        s0 = (int)e.x; s1 = (int)e.y; s2 = (int)f.x; s3 = (int)f.y;
    } else {
        int4 a = ((const int4*)((const int*)ei + N_EDGES))[tid];
        int4 e = ((const int4*)((const int*)ei))[tid];
        d0 = a.x; d1 = a.y; d2 = a.z; d3 = a.w;
        s0 = e.x; s1 = e.y; s2 = e.z; s3 = e.w;
    }
    int p0 = atomicAdd(&g_cursor[d0], 1); g_col[p0] = s0;
    int p1 = atomicAdd(&g_cursor[d1], 1); g_col[p1] = s1;
    int p2 = atomicAdd(&g_cursor[d2], 1); g_col[p2] = s2;
    int p3 = atomicAdd(&g_cursor[d3], 1); g_col[p3] = s3;
}

// ---------------- dense transform: ylh = fp16(h @ Wl.T), yr = h @ Wr.T ----------------
__global__ void __launch_bounds__(256) k_transform(
        const float* __restrict__ x_ext, int use_x,
        const float* __restrict__ Wl,
        const float* __restrict__ Wr) {
    __shared__ float sH[F * F];    // sH[k*64 + node]
    __shared__ float sWl[F * F];   // sWl[k*64 + c] = Wl[c*64 + k]
    __shared__ float sWr[F * F];
    const float* h = use_x ? x_ext : g_h;
    int t = threadIdx.x;
    int base = blockIdx.x * 64;

    for (int idx = t; idx < F * F; idx += 256) {
        int c = idx & 63, k = idx >> 6;
        sWl[k * F + c] = Wl[c * F + k];
        sWr[k * F + c] = Wr[c * F + k];
    }
    {
        int n = t & 63, kq = t >> 6;
        const float* hrow = h + (size_t)(base + n) * F;
        #pragma unroll
        for (int j = 0; j < 4; j++) {
            int kk = (kq + j * 4) * 4;
            float4 v = *(const float4*)(hrow + kk);
            sH[(kk + 0) * F + n] = v.x;
            sH[(kk + 1) * F + n] = v.y;
            sH[(kk + 2) * F + n] = v.z;
            sH[(kk + 3) * F + n] = v.w;
        }
    }
    __syncthreads();

    int tx = t & 15, ty = t >> 4;
    u64 al2[4][2], ar2[4][2];
    #pragma unroll
    for (int i = 0; i < 4; i++) {
        al2[i][0] = 0ull; al2[i][1] = 0ull;
        ar2[i][0] = 0ull; ar2[i][1] = 0ull;
    }

    #pragma unroll 8
    for (int k = 0; k < F; k++) {
        float4 a  = *(const float4*)&sH [k * F + ty * 4];
        float4 bl = *(const float4*)&sWl[k * F + tx * 4];
        float4 br = *(const float4*)&sWr[k * F + tx * 4];
        u64 b0 = pk2(bl.x, bl.y), b1 = pk2(bl.z, bl.w);
        u64 c0 = pk2(br.x, br.y), c1 = pk2(br.z, br.w);
        float av[4] = {a.x, a.y, a.z, a.w};
        #pragma unroll
        for (int i = 0; i < 4; i++) {
            u64 ai = pk2(av[i], av[i]);
            al2[i][0] = ffma2(ai, b0, al2[i][0]);
            al2[i][1] = ffma2(ai, b1, al2[i][1]);
            ar2[i][0] = ffma2(ai, c0, ar2[i][0]);
            ar2[i][1] = ffma2(ai, c1, ar2[i][1]);
        }
    }

    #pragma unroll
    for (int i = 0; i < 4; i++) {
        int node = base + ty * 4 + i;
        float l0, l1, l2, l3, r0, r1, r2, r3;
        upk2(al2[i][0], l0, l1); upk2(al2[i][1], l2, l3);
        upk2(ar2[i][0], r0, r1); upk2(ar2[i][1], r2, r3);
        // yl -> fp16 (gathered later); yr stays fp32
        __half2 h0 = __floats2half2_rn(l0, l1);
        __half2 h1 = __floats2half2_rn(l2, l3);
        *(__half2*)(g_ylh + (size_t)node * F + tx * 4)     = h0;
        *(__half2*)(g_ylh + (size_t)node * F + tx * 4 + 2) = h1;
        *(float4*)(g_yr + (size_t)node * F + tx * 4) = make_float4(r0, r1, r2, r3);
    }
}

// ---------------- aggregate + epilogue ----------------
// h = relu(invdeg * sum ylh[src] + yr + b); lane owns feature pair (2*lane, 2*lane+1)
// fuse_out: also compute y2l = h@Wlo.T, y2r = h@Wro.T via warp reduction and
//           skip the g_h store.
__global__ void k_aggr(const float* __restrict__ b,
                       const float* __restrict__ Wlo,
                       const float* __restrict__ Wro,
                       int fuse_out) {
    __shared__ float sw[4 * F];   // Wlo row0, Wlo row1, Wro row0, Wro row1
    if (fuse_out) {
        int t = threadIdx.x;
        if (t < 128) sw[t] = Wlo[t];
        else if (t < 256) sw[t] = Wro[t - 128];
        __syncthreads();
    }
    int warp = (blockIdx.x * blockDim.x + threadIdx.x) >> 5;
    int lane = threadIdx.x & 31;
    if (warp >= N_NODES) return;
    const __half2* yl = (const __half2*)g_ylh;   // 32 half2 per node row
    int s0 = g_rowptr[warp];
    int s1 = g_rowptr[warp + 1];
    float ax = 0.0f, ay = 0.0f;
    int j = s0;
    for (; j + 8 <= s1; j += 8) {
        int i0 = g_col[j + 0], i1 = g_col[j + 1], i2 = g_col[j + 2], i3 = g_col[j + 3];
        int i4 = g_col[j + 4], i5 = g_col[j + 5], i6 = g_col[j + 6], i7 = g_col[j + 7];
        __half2 v0 = yl[i0 * 32 + lane];
        __half2 v1 = yl[i1 * 32 + lane];
        __half2 v2 = yl[i2 * 32 + lane];
        __half2 v3 = yl[i3 * 32 + lane];
        __half2 v4 = yl[i4 * 32 + lane];
        __half2 v5 = yl[i5 * 32 + lane];
        __half2 v6 = yl[i6 * 32 + lane];
        __half2 v7 = yl[i7 * 32 + lane];
        float2 f0 = __half22float2(v0), f1 = __half22float2(v1);
        float2 f2 = __half22float2(v2), f3 = __half22float2(v3);
        float2 f4 = __half22float2(v4), f5 = __half22float2(v5);
        float2 f6 = __half22float2(v6), f7 = __half22float2(v7);
        ax += ((f0.x + f1.x) + (f2.x + f3.x)) + ((f4.x + f5.x) + (f6.x + f7.x));
        ay += ((f0.y + f1.y) + (f2.y + f3.y)) + ((f4.y + f5.y) + (f6.y + f7.y));
    }
    for (; j + 2 <= s1; j += 2) {
        int i0 = g_col[j], i1 = g_col[j + 1];
        float2 f0 = __half22float2(yl[i0 * 32 + lane]);
        float2 f1 = __half22float2(yl[i1 * 32 + lane]);
        ax += f0.x + f1.x;
        ay += f0.y + f1.y;
    }
    if (j < s1) {
        float2 f0 = __half22float2(yl[g_col[j] * 32 + lane]);
        ax += f0.x;
        ay += f0.y;
    }
    float id = g_invdeg[warp];
    float2 r = *(const float2*)(g_yr + (size_t)warp * F + lane * 2);
    float b0 = b[lane * 2], b1 = b[lane * 2 + 1];
    float o0 = fmaxf(ax * id + r.x + b0, 0.0f);
    float o1 = fmaxf(ay * id + r.y + b1, 0.0f);
    if (!fuse_out) {
        *(float2*)(g_h + (size_t)warp * F + lane * 2) = make_float2(o0, o1);
    } else {
        float p0 = o0 * sw[0 * F + lane * 2] + o1 * sw[0 * F + lane * 2 + 1];
        float p1 = o0 * sw[1 * F + lane * 2] + o1 * sw[1 * F + lane * 2 + 1];
        float p2 = o0 * sw[2 * F + lane * 2] + o1 * sw[2 * F + lane * 2 + 1];
        float p3 = o0 * sw[3 * F + lane * 2] + o1 * sw[3 * F + lane * 2 + 1];
        #pragma unroll
        for (int o = 16; o > 0; o >>= 1) {
            p0 += __shfl_xor_sync(0xffffffffu, p0, o);
            p1 += __shfl_xor_sync(0xffffffffu, p1, o);
            p2 += __shfl_xor_sync(0xffffffffu, p2, o);
            p3 += __shfl_xor_sync(0xffffffffu, p3, o);
        }
        if (lane == 0) {
            *(float2*)(g_y2l + (size_t)warp * 2) = make_float2(p0, p1);
            *(float2*)(g_y2r + (size_t)warp * 2) = make_float2(p2, p3);
        }
    }
}

// ---------------- output aggregation + graph pooling accumulate ----------------
__global__ void k_aggr_out(const void* __restrict__ batch,
                           const float* __restrict__ b_out) {
    int i = blockIdx.x * blockDim.x + threadIdx.x;
    if (i >= N_NODES) return;
    int s0 = g_rowptr[i];
    int s1 = g_rowptr[i + 1];
    float a0 = 0.0f, a1 = 0.0f;
    for (int j = s0; j < s1; j++) {
        int src = g_col[j];
        float2 v = *(const float2*)(g_y2l + (size_t)src * 2);
        a0 += v.x;
        a1 += v.y;
    }
    float id = g_invdeg[i];
    float o0 = a0 * id + g_y2r[i * 2 + 0] + b_out[0];
    float o1 = a1 * id + g_y2r[i * 2 + 1] + b_out[1];
    int g = idx_at(batch, i);
    atomicAdd(&g_gsum[g * 2 + 0], o0);
    atomicAdd(&g_gsum[g * 2 + 1], o1);
}

__global__ void k_final(float* __restrict__ out) {
    int i = threadIdx.x;
    if (i < N_GRAPHS * 2) {
        int g = i >> 1;
        float c = (float)max(g_gcnt[g], 1);
        out[i] = g_gsum[i] / c;
    }
}

// ---------------- launch ----------------
extern "C" void kernel_launch(void* const* d_in, const int* in_sizes, int n_in,
                              void* d_out, int out_size) {
    const float* x      = (const float*)d_in[0];
    const void*  ei     = d_in[1];   // int64 or int32 [2, E]
    const void*  batch  = d_in[2];   // int64 or int32 [N]
    const float* Wl     = (const float*)d_in[3];   // [3,64,64]
    const float* Wr     = (const float*)d_in[4];   // [3,64,64]
    const float* b      = (const float*)d_in[5];   // [3,64]
    const float* Wl_out = (const float*)d_in[6];   // [2,64]
    const float* Wr_out = (const float*)d_in[7];   // [2,64]
    const float* b_out  = (const float*)d_in[8];   // [2]
    float*       out    = (float*)d_out;

    // lazy one-time host resources (created on the uncaptured correctness run)
    static cudaStream_t s2 = 0;
    static cudaEvent_t ev0 = 0, ev1 = 0;
    if (s2 == 0) {
        cudaStreamCreateWithFlags(&s2, cudaStreamNonBlocking);
        cudaEventCreateWithFlags(&ev0, cudaEventDisableTiming);
        cudaEventCreateWithFlags(&ev1, cudaEventDisableTiming);
    }

    const int TGRID = N_NODES / 64;                 // 1000 blocks, 64 nodes each
    const int AGRID = (N_NODES * 32 + 255) / 256;   // warp per node

    // fork: transform layer 0 runs concurrently with the CSR build
    cudaEventRecord(ev0, 0);
    cudaStreamWaitEvent(s2, ev0, 0);
    k_transform<<<TGRID, 256, 0, s2>>>(x, 1, Wl + 0 * F * F, Wr + 0 * F * F);
    cudaEventRecord(ev1, s2);

    // CSR build chain on main stream
    k_init<<<SCAN_NB, 256>>>(ei);
    k_count<<<N_EDGES / 4 / 256, 256>>>(ei, batch);
    k_scan1<<<SCAN_NB, 256>>>();
    k_scan3<<<SCAN_NB, 256>>>();
    k_fill<<<N_EDGES / 4 / 256, 256>>>(ei);

    // join: aggregation layer 0 needs both CSR and transform0
    cudaStreamWaitEvent(0, ev1, 0);

    k_aggr<<<AGRID, 256>>>(b + 0 * F, Wl_out, Wr_out, 0);
    k_transform<<<TGRID, 256>>>(x, 0, Wl + 1 * F * F, Wr + 1 * F * F);
    k_aggr<<<AGRID, 256>>>(b + 1 * F, Wl_out, Wr_out, 0);
    k_transform<<<TGRID, 256>>>(x, 0, Wl + 2 * F * F, Wr + 2 * F * F);
    // layer 2: output-layer transform fused into the epilogue
    k_aggr<<<AGRID, 256>>>(b + 2 * F, Wl_out, Wr_out, 1);

    // output aggregation + global mean pool
    k_aggr_out<<<(N_NODES + 255) / 256, 256>>>(batch, b_out);
    k_final<<<1, 256>>>(out);
}